// round 3
// baseline (speedup 1.0000x reference)
#include <cuda_runtime.h>
#include <cooperative_groups.h>
#include <cstdint>

namespace cg = cooperative_groups;

namespace {
constexpr int   kB       = 8;
constexpr int   kNT      = 256;
constexpr int   kNZ      = 256;
constexpr int   kNX      = 256;
constexpr int   kNREC    = 64;
constexpr int   kThreads = 512;               // 2 groups of 256 (column = tid & 255)
constexpr float kDT2     = 1.0e-6f;           // DT*DT
constexpr float kInvDH2  = 0.01f;             // 1/(DH*DH)

constexpr int smem_floats(int cluster) {
    int rows = kNZ / cluster;
    int bufFloats = rows * kNX;
    // bufA, bufB, wav, recOff(64), recK(64), recCnt(1), pad(1), mbar(2 floats)
    return 2 * bufFloats + kNT + 64 + 64 + 2 + 2;
}
constexpr int smem_bytes(int cluster) { return smem_floats(cluster) * 4; }
}

__device__ __forceinline__ uint32_t smem_u32(const void* p) {
    uint32_t a;
    asm("{ .reg .u64 t; cvta.to.shared.u64 t, %1; cvt.u32.u64 %0, t; }"
        : "=r"(a) : "l"(p));
    return a;
}

// Post a release-scope arrival on the mbarrier at the same smem offset in CTA `rank`.
__device__ __forceinline__ void mbar_arrive_rank(uint32_t localAddr, uint32_t rank) {
    asm volatile(
        "{\n\t.reg .b32 ra;\n\t"
        "mapa.shared::cluster.u32 ra, %0, %1;\n\t"
        "mbarrier.arrive.release.cluster.shared::cluster.b64 _, [ra];\n\t}"
        :: "r"(localAddr), "r"(rank) : "memory");
}

// Acquire-scope parity wait on the local mbarrier.
__device__ __forceinline__ void mbar_wait(uint32_t addr, uint32_t parity) {
    uint32_t done;
    asm volatile(
        "{\n\t.reg .pred p;\n\t"
        "mbarrier.try_wait.parity.acquire.cluster.shared::cta.b64 p, [%1], %2;\n\t"
        "selp.b32 %0, 1, 0, p;\n\t}"
        : "=r"(done) : "r"(addr), "r"(parity) : "memory");
    if (!done) {
        asm volatile(
            "{\n\t.reg .pred P1;\n\t"
            "WAVE_WAIT_%=:\n\t"
            "mbarrier.try_wait.parity.acquire.cluster.shared::cta.b64 P1, [%0], %1, 0x989680;\n\t"
            "@P1 bra.uni WAVE_DONE_%=;\n\t"
            "bra.uni WAVE_WAIT_%=;\n\t"
            "WAVE_DONE_%=:\n\t}"
            :: "r"(addr), "r"(parity) : "memory");
    }
}

template <int CLUSTER>
__global__ void __launch_bounds__(kThreads, 1)
wave_fd_kernel(const float* __restrict__ x,
               const float* __restrict__ vp,
               const int*   __restrict__ src_loc,
               const int*   __restrict__ rec_loc,
               float*       __restrict__ out)
{
    constexpr int kRows = kNZ / CLUSTER;      // rows per CTA
    constexpr int kHalf = kRows / 2;          // rows per thread
    constexpr int kBufFloats = kRows * kNX;
    constexpr int kWavOff = 2 * kBufFloats;
    constexpr int kIntOff = kWavOff + kNT;    // even -> 8B-alignable below

    extern __shared__ float sm[];
    float* bufA   = sm;
    float* bufB   = sm + kBufFloats;
    float* wav    = sm + kWavOff;
    int*   recOff = (int*)(sm + kIntOff);
    int*   recK   = recOff + 64;
    int*   recCnt = recK + 64;
    unsigned long long* mbar = (unsigned long long*)(sm + kIntOff + 130); // 8B aligned

    cg::cluster_group cluster = cg::this_cluster();
    const int rank  = (int)cluster.block_rank();
    const int batch = blockIdx.x / CLUSTER;
    const int tid   = threadIdx.x;
    const int c     = tid & (kNX - 1);        // column 0..255
    const int g     = tid >> 8;               // which half of the slab
    const int gz0   = rank * kRows + g * kHalf;

    const uint32_t mbarAddr = smem_u32(mbar);

    // ---- init: zero ping-pong buffers, wavelet, receiver list, mbarrier ----
    for (int i = tid; i < 2 * kBufFloats; i += kThreads) sm[i] = 0.0f;
    if (tid < kNT) wav[tid] = x[batch * kNT + tid];
    if (tid == 0) {
        *recCnt = 0;
        asm volatile("mbarrier.init.shared.b64 [%0], %1;"
                     :: "r"(mbarAddr), "r"(2u) : "memory");
    }
    __syncthreads();
    if (tid < kNREC) {
        int rz = rec_loc[(batch * kNREC + tid) * 2 + 0];
        int rx = rec_loc[(batch * kNREC + tid) * 2 + 1];
        if (rz >= rank * kRows && rz < (rank + 1) * kRows) {
            int slot = atomicAdd(recCnt, 1);
            recOff[slot] = (rz - rank * kRows) * kNX + rx;
            recK[slot]   = tid;
        }
    }
    __syncthreads();
    const int cnt = *recCnt;

    // ---- source ownership ----
    const int  sz     = src_loc[batch * 2 + 0];
    const int  sx     = src_loc[batch * 2 + 1];
    const bool isSrc  = (c == sx) && (sz >= gz0) && (sz < gz0 + kHalf);
    const int  srcOff = (sz - rank * kRows) * kNX + c;

    // ---- per-cell coefficients and h^{t-1} in registers ----
    float c2[kHalf], h2[kHalf];
#pragma unroll
    for (int i = 0; i < kHalf; i++) {
        float v = vp[(gz0 + i) * kNX + c];
        c2[i] = v * v * kDT2;
        h2[i] = 0.0f;
    }

    const bool active    = (c > 0) && (c < kNX - 1);
    const bool skipFirst = (rank == 0) && (g == 0);            // global row 0
    const bool skipLast  = (rank == CLUSTER - 1) && (g == 1);  // global row NZ-1

    // ---- DSMEM neighbor pointers (clamped at cluster edges) ----
    const int prevRank = (rank == 0) ? 0 : rank - 1;
    const int nextRank = (rank == CLUSTER - 1) ? rank : rank + 1;
    const float* prevA = cluster.map_shared_rank(bufA, prevRank);
    const float* prevB = cluster.map_shared_rank(bufB, prevRank);
    const float* nextA = cluster.map_shared_rank(bufA, nextRank);
    const float* nextB = cluster.map_shared_rank(bufB, nextRank);

    cluster.sync();   // buffers zeroed + mbarriers initialized cluster-wide

    const int strip = g * kHalf * kNX + c;
    uint32_t phase = 0;

    for (int t = 0; t < kNT; t++) {
        const float* cur     = (t & 1) ? bufB : bufA;
        float*       nxt     = (t & 1) ? bufA : bufB;
        const float* prevCur = (t & 1) ? prevB : prevA;
        const float* nextCur = (t & 1) ? nextB : nextA;

        if (active) {
            const float* cb = cur + strip;
            float*       nb = nxt + strip;

            // one DSMEM halo load per thread (issued first, consumed per row)
            float halo = (g == 0) ? prevCur[(kRows - 1) * kNX + c]
                                  : nextCur[c];

            float cm1 = (g == 0) ? halo : cb[-kNX];
            float c0  = cb[0];
#pragma unroll
            for (int i = 0; i < kHalf; i++) {
                float cp1;
                if (i < kHalf - 1)  cp1 = cb[(i + 1) * kNX];
                else if (g == 0)    cp1 = cb[kHalf * kNX];   // first row of g=1 half
                else                cp1 = halo;              // next CTA's row 0
                float l   = cb[i * kNX - 1];
                float r   = cb[i * kNX + 1];
                float lap = ((cm1 + cp1) + (l + r) - 4.0f * c0) * kInvDH2;
                float hn  = fmaf(c2[i], lap, 2.0f * c0 - h2[i]);
                h2[i] = c0;
                bool store = true;
                if (i == 0         && skipFirst) store = false;
                if (i == kHalf - 1 && skipLast)  store = false;
                if (store) nb[i * kNX] = hn;
                cm1 = c0; c0 = cp1;
            }
            if (isSrc) nxt[srcOff] += kDT2 * wav[t];
        }

        // CTA-local completion: all writes to nxt + all halo reads done.
        __syncthreads();

        // Signal both neighbors: "my step t is fully done" (release, cluster scope).
        if (tid == 0) {
            mbar_arrive_rank(mbarAddr, (uint32_t)prevRank);
            mbar_arrive_rank(mbarAddr, (uint32_t)nextRank);
        }

        // Receiver gather overlaps with the neighbor wait (own-CTA smem only).
        if (tid < cnt)
            out[(batch * kNT + t) * kNREC + recK[tid]] = nxt[recOff[tid]];

        // Wait for both neighbors to finish step t (acquire, cluster scope).
        mbar_wait(mbarAddr, phase);
        phase ^= 1;
    }
}

extern "C" void kernel_launch(void* const* d_in, const int* in_sizes, int n_in,
                              void* d_out, int out_size)
{
    (void)in_sizes; (void)n_in; (void)out_size;
    const float* x   = (const float*)d_in[0];
    const float* vp  = (const float*)d_in[1];
    const int*   src = (const int*)d_in[2];
    const int*   rec = (const int*)d_in[3];
    float*       out = (float*)d_out;

    cudaFuncSetAttribute(wave_fd_kernel<16>,
                         cudaFuncAttributeMaxDynamicSharedMemorySize, smem_bytes(16));
    cudaFuncSetAttribute(wave_fd_kernel<16>,
                         cudaFuncAttributeNonPortableClusterSizeAllowed, 1);
    cudaFuncSetAttribute(wave_fd_kernel<8>,
                         cudaFuncAttributeMaxDynamicSharedMemorySize, smem_bytes(8));

    int maxCluster = 0;
    {
        cudaLaunchConfig_t probe = {};
        probe.gridDim          = dim3(kB * 16, 1, 1);
        probe.blockDim         = dim3(kThreads, 1, 1);
        probe.dynamicSmemBytes = smem_bytes(16);
        cudaOccupancyMaxPotentialClusterSize(&maxCluster, (const void*)wave_fd_kernel<16>, &probe);
    }

    cudaLaunchAttribute attr[1];
    attr[0].id = cudaLaunchAttributeClusterDimension;
    attr[0].val.clusterDim.y = 1;
    attr[0].val.clusterDim.z = 1;

    cudaLaunchConfig_t cfg = {};
    cfg.blockDim = dim3(kThreads, 1, 1);
    cfg.stream   = 0;
    cfg.attrs    = attr;
    cfg.numAttrs = 1;

    if (maxCluster >= 16) {
        cfg.gridDim              = dim3(kB * 16, 1, 1);
        cfg.dynamicSmemBytes     = smem_bytes(16);
        attr[0].val.clusterDim.x = 16;
        cudaLaunchKernelEx(&cfg, wave_fd_kernel<16>, x, vp, src, rec, out);
    } else {
        cfg.gridDim              = dim3(kB * 8, 1, 1);
        cfg.dynamicSmemBytes     = smem_bytes(8);
        attr[0].val.clusterDim.x = 8;
        cudaLaunchKernelEx(&cfg, wave_fd_kernel<8>, x, vp, src, rec, out);
    }
}